// round 4
// baseline (speedup 1.0000x reference)
#include <cuda_runtime.h>
#include <stdint.h>

#define NODES   100000
#define MAX_E   3200000
#define SCAN_BS 1024
#define NB      ((NODES + SCAN_BS - 1) / SCAN_BS)   // 98
#define TILE    128
#define NT_TILES 8
#define K4_THREADS 256
#define FSTRIDE 72
#define CSTRIDE 20
#define DEN_FX  16777216.0f

// ---------------- scratch ----------------
__device__ unsigned long long g_cd[NODES];   // hi32=count, lo32=den (2^-24 fixed)
__device__ int   g_cursor[NODES];
__device__ float g_invden[NODES];
__device__ int   g_bsum[NB];
__device__ uint4 g_pack[MAX_E];              // {eid, node, bits(w), 0}

// ---------------- helpers ----------------
__device__ __forceinline__ unsigned f2tf32(float f) {
    unsigned r;
    asm("cvt.rna.tf32.f32 %0, %1;" : "=r"(r) : "f"(f));
    return r;
}
__device__ __forceinline__ void mma_tf32(float& d0, float& d1, float& d2, float& d3,
                                         unsigned a0, unsigned a1, unsigned a2, unsigned a3,
                                         unsigned b0, unsigned b1) {
    asm volatile(
        "mma.sync.aligned.m16n8k8.row.col.f32.tf32.tf32.f32 "
        "{%0,%1,%2,%3}, {%4,%5,%6,%7}, {%8,%9}, {%0,%1,%2,%3};"
        : "+f"(d0), "+f"(d1), "+f"(d2), "+f"(d3)
        : "r"(a0), "r"(a1), "r"(a2), "r"(a3), "r"(b0), "r"(b1));
}

// ---------------- K1: count + weight-sum + zero out[] ----------------
__global__ void k_count(const int* __restrict__ idx, const float* __restrict__ w,
                        float4* __restrict__ out4, int n4, int E) {
    int e = blockIdx.x * blockDim.x + threadIdx.x;
    for (int z = e; z < n4; z += gridDim.x * blockDim.x)
        out4[z] = make_float4(0.f, 0.f, 0.f, 0.f);
    if (e >= E) return;
    int n = idx[e];
    unsigned fx = __float2uint_rn(w[e] * DEN_FX);
    atomicAdd(&g_cd[n], (1ULL << 32) | (unsigned long long)fx);
}

// ---------------- K2: block-local scan + invden + g_cd re-zero ----------------
__global__ void k_scan1() {
    __shared__ int wsum[32];
    int t = threadIdx.x, b = blockIdx.x;
    int i = b * SCAN_BS + t;
    int lane = t & 31, wq = t >> 5;
    unsigned long long cd = (i < NODES) ? g_cd[i] : 0ULL;
    int v = (int)(cd >> 32);
    if (i < NODES) {
        g_cd[i] = 0ULL;
        g_invden[i] = __fdividef(DEN_FX, (float)(unsigned)(cd & 0xffffffffULL));
    }
    int x = v;
#pragma unroll
    for (int d = 1; d < 32; d <<= 1) {
        int y = __shfl_up_sync(0xffffffffu, x, d);
        if (lane >= d) x += y;
    }
    if (lane == 31) wsum[wq] = x;
    __syncthreads();
    if (wq == 0) {
        int s = wsum[lane];
#pragma unroll
        for (int d = 1; d < 32; d <<= 1) {
            int y = __shfl_up_sync(0xffffffffu, s, d);
            if (lane >= d) s += y;
        }
        wsum[lane] = s;
    }
    __syncthreads();
    int base = wq ? wsum[wq - 1] : 0;
    if (i < NODES) g_cursor[i] = base + x - v;   // block-local exclusive
    if (t == 0) g_bsum[b] = wsum[31];
}

// ---------------- K3: scatter (inline bsum prefix; global pos = local + boff) ----------------
__global__ void k_scatter(const int* __restrict__ idx, const float* __restrict__ w, int E) {
    __shared__ int s_boff[128];
    __shared__ int s_wt[4];
    int t = threadIdx.x;
    int lane = t & 31, wq = t >> 5;
    int v = 0, x = 0;
    if (t < 128) {
        v = (t < NB) ? g_bsum[t] : 0;
        x = v;
#pragma unroll
        for (int d = 1; d < 32; d <<= 1) {
            int y = __shfl_up_sync(0xffffffffu, x, d);
            if (lane >= d) x += y;
        }
        if (lane == 31) s_wt[wq] = x;
    }
    __syncthreads();
    if (t < 128) {
        int addv = 0;
#pragma unroll
        for (int k = 0; k < 4; k++) if (k < wq) addv += s_wt[k];
        s_boff[t] = addv + x - v;   // exclusive prefix of block sums
    }
    __syncthreads();
    int e = blockIdx.x * blockDim.x + t;
    if (e >= E) return;
    int n = idx[e];
    int p = atomicAdd(&g_cursor[n], 1) + s_boff[n >> 10];
    g_pack[p] = make_uint4((unsigned)e, (unsigned)n, __float_as_uint(w[e]), 0u);
}

// ---------------- K4: persistent pipelined MMA + segmented reduction ----------------
__global__ void __launch_bounds__(K4_THREADS, 2)
k_main(const float* __restrict__ emb, const float* __restrict__ cf,
       float* __restrict__ out, int E) {
    __shared__ __align__(16) float    s_feats[TILE * FSTRIDE];   // 36864 B
    __shared__ __align__(16) unsigned s_emb[64 * CSTRIDE];       // 5120 B
    __shared__ int   s_node[TILE];
    __shared__ float s_w[TILE];
    __shared__ float s_pbuf[16][64];
    __shared__ int   s_pn[16];
    __shared__ int   s_ev[16];
    unsigned* s_cf = (unsigned*)s_feats;

    int t = threadIdx.x, wp = t >> 5, l = t & 31;
    int ii = t & 127, half = t >> 7;
    int c = l & 3, r4 = l >> 2;
    int blkbase = blockIdx.x * (NT_TILES * TILE);

    // --- embedding -> smem tf32, once ---
    for (int j = t; j < 64 * 16; j += K4_THREADS)
        s_emb[(j >> 4) * CSTRIDE + (j & 15)] = f2tf32(emb[j]);
    __syncthreads();

    // --- B fragments -> registers, once ---
    unsigned B[8][4];
#pragma unroll
    for (int nt = 0; nt < 8; nt++) {
        int er = nt * 8 + r4;
        B[nt][0] = s_emb[er * CSTRIDE + c];
        B[nt][1] = s_emb[er * CSTRIDE + c + 4];
        B[nt][2] = s_emb[er * CSTRIDE + c + 8];
        B[nt][3] = s_emb[er * CSTRIDE + c + 12];
    }

    // --- pipeline prologue: tile 0 gather + tile 1 pack ---
    float4 cp0 = make_float4(0.f, 0.f, 0.f, 0.f), cp1 = cp0;
    unsigned curNode = 0u, curW = 0u;
    {
        int g = blkbase + ii;
        uint4 pk = make_uint4(0u, 0u, 0u, 0u);
        if (g < E) pk = g_pack[g];
        curNode = pk.y; curW = pk.z;
        if (g < E) {
            const float4* cp = (const float4*)(cf + (size_t)pk.x * 16);
            cp0 = cp[half * 2]; cp1 = cp[half * 2 + 1];
        }
    }
    uint4 pkA = make_uint4(0u, 0u, 0u, 0u);
    {
        int g1 = blkbase + TILE + ii;
        if (NT_TILES > 1 && g1 < E) pkA = g_pack[g1];
    }

    for (int j = 0; j < NT_TILES; j++) {
        int tbase = blkbase + j * TILE;
        if (tbase >= E) break;

        // --- stage current tile into smem ---
        if (half == 0) { s_node[ii] = (int)curNode; s_w[ii] = __uint_as_float(curW); }
        {
            unsigned q0 = f2tf32(cp0.x), q1 = f2tf32(cp0.y), q2 = f2tf32(cp0.z), q3 = f2tf32(cp0.w);
            unsigned q4 = f2tf32(cp1.x), q5 = f2tf32(cp1.y), q6 = f2tf32(cp1.z), q7 = f2tf32(cp1.w);
            unsigned* dst = s_cf + ii * CSTRIDE + half * 8;
            *(uint4*)(dst)     = make_uint4(q0, q1, q2, q3);
            *(uint4*)(dst + 4) = make_uint4(q4, q5, q6, q7);
        }
        if (t < 16) s_ev[t] = 0;
        __syncthreads();

        // --- A fragments ---
        int row = wp * 16 + r4;
        unsigned a0 = s_cf[row * CSTRIDE + c];
        unsigned a1 = s_cf[(row + 8) * CSTRIDE + c];
        unsigned a2 = s_cf[row * CSTRIDE + c + 4];
        unsigned a3 = s_cf[(row + 8) * CSTRIDE + c + 4];
        unsigned a4 = s_cf[row * CSTRIDE + c + 8];
        unsigned a5 = s_cf[(row + 8) * CSTRIDE + c + 8];
        unsigned a6 = s_cf[row * CSTRIDE + c + 12];
        unsigned a7 = s_cf[(row + 8) * CSTRIDE + c + 12];
        float w_lo = s_w[row], w_hi = s_w[row + 8];
        __syncthreads();   // frags in regs before s_feats overwrites aliased s_cf

        // --- prefetch: gather tile j+1 (pack already in pkA), pack tile j+2 ---
        curNode = pkA.y; curW = pkA.z;
        {
            cp0 = make_float4(0.f, 0.f, 0.f, 0.f); cp1 = cp0;
            int gn = tbase + TILE + ii;
            if (j + 1 < NT_TILES && gn < E) {
                const float4* cp = (const float4*)(cf + (size_t)pkA.x * 16);
                cp0 = cp[half * 2]; cp1 = cp[half * 2 + 1];
            }
            int g2 = tbase + 2 * TILE + ii;
            pkA = make_uint4(0u, 0u, 0u, 0u);
            if (j + 2 < NT_TILES && g2 < E) pkA = g_pack[g2];
        }

        // --- 16 MMAs/warp ---
#pragma unroll
        for (int nt = 0; nt < 8; nt++) {
            float d0 = 0.f, d1 = 0.f, d2 = 0.f, d3 = 0.f;
            mma_tf32(d0, d1, d2, d3, a0, a1, a2, a3, B[nt][0], B[nt][1]);
            mma_tf32(d0, d1, d2, d3, a4, a5, a6, a7, B[nt][2], B[nt][3]);
            d0 = fmaxf(d0, 0.f) * w_lo;
            d1 = fmaxf(d1, 0.f) * w_lo;
            d2 = fmaxf(d2, 0.f) * w_hi;
            d3 = fmaxf(d3, 0.f) * w_hi;
            int col = nt * 8 + 2 * c;
            *(float2*)&s_feats[row * FSTRIDE + col]       = make_float2(d0, d1);
            *(float2*)&s_feats[(row + 8) * FSTRIDE + col] = make_float2(d2, d3);
        }
        __syncthreads();

        // --- phase 1: 8 warps x 16 rows ---
        int vr = min(TILE, E - tbase);
        int lo = wp * 16;
        if (lo < vr) {
            int hi = min(lo + 16, vr);
            int n0 = s_node[lo];
            if (s_node[hi - 1] == n0) {
                // fast path: uniform span, branch-free 4-way sum
                float2 ac[4];
#pragma unroll
                for (int k = 0; k < 4; k++) ac[k] = make_float2(0.f, 0.f);
#pragma unroll
                for (int r = 0; r < 16; r++) {
                    if (lo + r < hi) {
                        float2 vv = *(float2*)&s_feats[(lo + r) * FSTRIDE + 2 * l];
                        ac[r & 3].x += vv.x; ac[r & 3].y += vv.y;
                    }
                }
                float2 acc = make_float2(ac[0].x + ac[1].x + ac[2].x + ac[3].x,
                                         ac[0].y + ac[1].y + ac[2].y + ac[3].y);
                s_pbuf[2 * wp + 1][2 * l]     = acc.x;
                s_pbuf[2 * wp + 1][2 * l + 1] = acc.y;
                if (l == 0) { s_pn[2 * wp + 1] = n0; s_ev[2 * wp + 1] = 1; }
            } else {
                int cur = n0;
                float2 acc = make_float2(0.f, 0.f);
                int nseg = 0;
                for (int r = lo; r < hi; r++) {
                    int nd = s_node[r];
                    if (nd != cur) {
                        if (nseg == 0) {
                            s_pbuf[2 * wp][2 * l]     = acc.x;
                            s_pbuf[2 * wp][2 * l + 1] = acc.y;
                            if (l == 0) { s_pn[2 * wp] = cur; s_ev[2 * wp] = 1; }
                        } else {
                            float invd = g_invden[cur];
                            *(float2*)(out + (size_t)cur * 64 + 2 * l) =
                                make_float2(acc.x * invd, acc.y * invd);
                        }
                        nseg++;
                        cur = nd;
                        acc = make_float2(0.f, 0.f);
                    }
                    float2 vv = *(float2*)&s_feats[r * FSTRIDE + 2 * l];
                    acc.x += vv.x; acc.y += vv.y;
                }
                s_pbuf[2 * wp + 1][2 * l]     = acc.x;
                s_pbuf[2 * wp + 1][2 * l + 1] = acc.y;
                if (l == 0) { s_pn[2 * wp + 1] = cur; s_ev[2 * wp + 1] = 1; }
            }
        }
        __syncthreads();

        // --- phase 2: warp 0 merges <=16 boundary partials in order ---
        if (wp == 0) {
            int cur = -1;
            float2 acc = make_float2(0.f, 0.f);
            bool first = true;
#pragma unroll
            for (int e2 = 0; e2 < 16; e2++) {
                if (!s_ev[e2]) continue;
                int nd = s_pn[e2];
                float2 vv = *(float2*)&s_pbuf[e2][2 * l];
                if (nd != cur) {
                    if (cur >= 0) {
                        float invd = g_invden[cur];
                        float* dst = out + (size_t)cur * 64 + 2 * l;
                        if (first) {
                            atomicAdd(dst, acc.x * invd);
                            atomicAdd(dst + 1, acc.y * invd);
                            first = false;
                        } else {
                            *(float2*)dst = make_float2(acc.x * invd, acc.y * invd);
                        }
                    }
                    cur = nd;
                    acc = vv;
                } else { acc.x += vv.x; acc.y += vv.y; }
            }
            float invd = g_invden[cur];
            float* dst = out + (size_t)cur * 64 + 2 * l;
            atomicAdd(dst, acc.x * invd);
            atomicAdd(dst + 1, acc.y * invd);
        }
    }
}

// ---------------- launch ----------------
extern "C" void kernel_launch(void* const* d_in, const int* in_sizes, int n_in,
                              void* d_out, int out_size) {
    const float* emb = (const float*)d_in[0];   // [64,16]
    const float* cf  = (const float*)d_in[1];   // [E,16]
    const float* w   = (const float*)d_in[2];   // [E]
    const int*   idx = (const int*)d_in[3];     // [E]
    int E = in_sizes[2];
    float* out = (float*)d_out;                 // [100000,64]

    int eb = (E + 255) / 256;
    int n4 = out_size / 4;

    k_count<<<eb, 256>>>(idx, w, (float4*)d_out, n4, E);
    k_scan1<<<NB, SCAN_BS>>>();
    k_scatter<<<eb, 256>>>(idx, w, E);

    int nb4 = (E + TILE * NT_TILES - 1) / (TILE * NT_TILES);
    k_main<<<nb4, K4_THREADS>>>(emb, cf, out, E);
}

// round 5
// speedup vs baseline: 1.5229x; 1.5229x over previous
#include <cuda_runtime.h>
#include <stdint.h>

#define NODES   100000
#define MAX_E   3200000
#define SCAN_BS 1024
#define NB      ((NODES + SCAN_BS - 1) / SCAN_BS)   // 98
#define CSTRIDE 20
#define FSTRIDE 72
#define DEN_FX  16777216.0f

// ---------------- scratch ----------------
__device__ unsigned long long g_cd[NODES];   // hi32=count, lo32=den (2^-24 fixed)
__device__ int   g_cursor[NODES];
__device__ float g_invden[NODES];
__device__ int   g_bsum[NB];
__device__ uint4 g_pack[MAX_E];              // {eid, node, bits(w), 0}

// ---------------- helpers ----------------
__device__ __forceinline__ unsigned f2tf32(float f) {
    unsigned r;
    asm("cvt.rna.tf32.f32 %0, %1;" : "=r"(r) : "f"(f));
    return r;
}
__device__ __forceinline__ void mma_tf32(float& d0, float& d1, float& d2, float& d3,
                                         unsigned a0, unsigned a1, unsigned a2, unsigned a3,
                                         unsigned b0, unsigned b1) {
    asm volatile(
        "mma.sync.aligned.m16n8k8.row.col.f32.tf32.tf32.f32 "
        "{%0,%1,%2,%3}, {%4,%5,%6,%7}, {%8,%9}, {%0,%1,%2,%3};"
        : "+f"(d0), "+f"(d1), "+f"(d2), "+f"(d3)
        : "r"(a0), "r"(a1), "r"(a2), "r"(a3), "r"(b0), "r"(b1));
}

// ---------------- K1: count + weight-sum + zero out[] ----------------
__global__ void k_count(const int* __restrict__ idx, const float* __restrict__ w,
                        float4* __restrict__ out4, int n4, int E) {
    int e = blockIdx.x * blockDim.x + threadIdx.x;
    for (int z = e; z < n4; z += gridDim.x * blockDim.x)
        out4[z] = make_float4(0.f, 0.f, 0.f, 0.f);
    if (e >= E) return;
    int n = idx[e];
    unsigned fx = __float2uint_rn(w[e] * DEN_FX);
    atomicAdd(&g_cd[n], (1ULL << 32) | (unsigned long long)fx);
}

// ---------------- K2: block-local scan + invden + g_cd re-zero ----------------
__global__ void k_scan1() {
    __shared__ int wsum[32];
    int t = threadIdx.x, b = blockIdx.x;
    int i = b * SCAN_BS + t;
    int lane = t & 31, wq = t >> 5;
    unsigned long long cd = (i < NODES) ? g_cd[i] : 0ULL;
    int v = (int)(cd >> 32);
    if (i < NODES) {
        g_cd[i] = 0ULL;
        g_invden[i] = __fdividef(DEN_FX, (float)(unsigned)(cd & 0xffffffffULL));
    }
    int x = v;
#pragma unroll
    for (int d = 1; d < 32; d <<= 1) {
        int y = __shfl_up_sync(0xffffffffu, x, d);
        if (lane >= d) x += y;
    }
    if (lane == 31) wsum[wq] = x;
    __syncthreads();
    if (wq == 0) {
        int s = wsum[lane];
#pragma unroll
        for (int d = 1; d < 32; d <<= 1) {
            int y = __shfl_up_sync(0xffffffffu, s, d);
            if (lane >= d) s += y;
        }
        wsum[lane] = s;
    }
    __syncthreads();
    int base = wq ? wsum[wq - 1] : 0;
    if (i < NODES) g_cursor[i] = base + x - v;
    if (t == 0) g_bsum[b] = wsum[31];
}

// ---------------- K3: scatter (inline bsum prefix) ----------------
__global__ void k_scatter(const int* __restrict__ idx, const float* __restrict__ w, int E) {
    __shared__ int s_boff[128];
    __shared__ int s_wt[4];
    int t = threadIdx.x;
    int lane = t & 31, wq = t >> 5;
    int v = 0, x = 0;
    if (t < 128) {
        v = (t < NB) ? g_bsum[t] : 0;
        x = v;
#pragma unroll
        for (int d = 1; d < 32; d <<= 1) {
            int y = __shfl_up_sync(0xffffffffu, x, d);
            if (lane >= d) x += y;
        }
        if (lane == 31) s_wt[wq] = x;
    }
    __syncthreads();
    if (t < 128) {
        int addv = 0;
#pragma unroll
        for (int k = 0; k < 4; k++) if (k < wq) addv += s_wt[k];
        s_boff[t] = addv + x - v;
    }
    __syncthreads();
    int e = blockIdx.x * blockDim.x + t;
    if (e >= E) return;
    int n = idx[e];
    int p = atomicAdd(&g_cursor[n], 1) + s_boff[n >> 10];
    g_pack[p] = make_uint4((unsigned)e, (unsigned)n, __float_as_uint(w[e]), 0u);
}

// ---------------- K4: warp-autonomous MMA + segmented reduce (no block syncs) ----------------
__global__ void __launch_bounds__(256, 4)
k_main(const float* __restrict__ emb, const float* __restrict__ cf,
       float* __restrict__ out, int E) {
    __shared__ __align__(16) unsigned s_emb[64 * CSTRIDE];      // 5120 B
    __shared__ __align__(16) float    s_f[8][16 * FSTRIDE];     // 8 x 4608 B

    int t = threadIdx.x, wp = t >> 5, l = t & 31;
    int c = l & 3, r4 = l >> 2;

    // stage embedding once (only block-wide sync in the kernel)
    for (int j = t; j < 64 * 16; j += 256)
        s_emb[(j >> 4) * CSTRIDE + (j & 15)] = f2tf32(emb[j]);
    __syncthreads();

    int wbase = blockIdx.x * 128 + wp * 16;

    // --- pack: lanes 0-15 hold rows 0-15 of this window ---
    uint4 pk = make_uint4(0u, 0u, 0u, 0u);
    if (l < 16 && wbase + l < E) pk = g_pack[wbase + l];
    unsigned eid_lo = __shfl_sync(0xffffffffu, pk.x, r4);
    unsigned eid_hi = __shfl_sync(0xffffffffu, pk.x, r4 + 8);
    float w_lo = __uint_as_float(__shfl_sync(0xffffffffu, pk.z, r4));
    float w_hi = __uint_as_float(__shfl_sync(0xffffffffu, pk.z, r4 + 8));
    int nd = (int)pk.y;                                   // node of row l (lanes 0-15)
    int ndn = __shfl_down_sync(0xffffffffu, nd, 1);
    unsigned bm = __ballot_sync(0xffffffffu, (l < 15) && (nd != ndn)) & 0x7fffu;

    // --- direct A-fragment gather: 8 LDG.32 per lane, ~600cyc hidden by 32 warps/SM ---
    const float* plo = cf + (size_t)eid_lo * 16 + c;
    const float* phi = cf + (size_t)eid_hi * 16 + c;
    float f0 = plo[0], f2 = plo[4], f4 = plo[8], f6 = plo[12];
    float f1 = phi[0], f3 = phi[4], f5 = phi[8], f7 = phi[12];
    unsigned a0 = f2tf32(f0), a2 = f2tf32(f2), a4 = f2tf32(f4), a6 = f2tf32(f6);
    unsigned a1 = f2tf32(f1), a3 = f2tf32(f3), a5 = f2tf32(f5), a7 = f2tf32(f7);

    // --- 16 MMAs: 16 edges x 64 u; relu * w -> per-warp smem transpose ---
    float* sf = s_f[wp];
#pragma unroll
    for (int nt = 0; nt < 8; nt++) {
        int er = nt * 8 + r4;
        unsigned b0 = s_emb[er * CSTRIDE + c];
        unsigned b1 = s_emb[er * CSTRIDE + c + 4];
        unsigned b2 = s_emb[er * CSTRIDE + c + 8];
        unsigned b3 = s_emb[er * CSTRIDE + c + 12];
        float d0 = 0.f, d1 = 0.f, d2 = 0.f, d3 = 0.f;
        mma_tf32(d0, d1, d2, d3, a0, a1, a2, a3, b0, b1);
        mma_tf32(d0, d1, d2, d3, a4, a5, a6, a7, b2, b3);
        d0 = fmaxf(d0, 0.f) * w_lo;
        d1 = fmaxf(d1, 0.f) * w_lo;
        d2 = fmaxf(d2, 0.f) * w_hi;
        d3 = fmaxf(d3, 0.f) * w_hi;
        int col = nt * 8 + 2 * c;
        *(float2*)&sf[r4 * FSTRIDE + col]       = make_float2(d0, d1);
        *(float2*)&sf[(r4 + 8) * FSTRIDE + col] = make_float2(d2, d3);
    }
    __syncwarp();

    // --- segmented reduce: lane l owns cols 2l,2l+1; out addr = node*64+2l (coalesced) ---
    // unscaled sums; k_scale applies 1/den afterwards. first/last segment may span
    // window boundaries -> red.add; interior segments are exclusively ours -> STG.
    float2 acc = make_float2(0.f, 0.f);
    int s = 0;
    bool first = true;
#pragma unroll
    for (int r = 0; r < 16; r++) {
        float2 v = *(float2*)&sf[r * FSTRIDE + 2 * l];
        acc.x += v.x; acc.y += v.y;
        if (bm & (1u << r)) {                      // warp-uniform branch
            int segn = __shfl_sync(0xffffffffu, nd, s);
            float* dst = out + (size_t)segn * 64 + 2 * l;
            if (first)
                asm volatile("red.global.add.v2.f32 [%0], {%1,%2};"
                             :: "l"(dst), "f"(acc.x), "f"(acc.y) : "memory");
            else
                *(float2*)dst = acc;
            first = false;
            acc = make_float2(0.f, 0.f);
            s = r + 1;
        }
    }
    {
        int segn = __shfl_sync(0xffffffffu, nd, s);
        float* dst = out + (size_t)segn * 64 + 2 * l;
        asm volatile("red.global.add.v2.f32 [%0], {%1,%2};"
                     :: "l"(dst), "f"(acc.x), "f"(acc.y) : "memory");
    }
}

// ---------------- K5: epilogue scale out *= 1/den ----------------
__global__ void k_scale(float4* __restrict__ out4, int n4) {
    int i = blockIdx.x * blockDim.x + threadIdx.x;
    if (i >= n4) return;
    float s = g_invden[i >> 4];          // 16 float4 per node
    float4 v = out4[i];
    v.x *= s; v.y *= s; v.z *= s; v.w *= s;
    out4[i] = v;
}

// ---------------- launch ----------------
extern "C" void kernel_launch(void* const* d_in, const int* in_sizes, int n_in,
                              void* d_out, int out_size) {
    const float* emb = (const float*)d_in[0];   // [64,16]
    const float* cf  = (const float*)d_in[1];   // [E,16]
    const float* w   = (const float*)d_in[2];   // [E]
    const int*   idx = (const int*)d_in[3];     // [E]
    int E = in_sizes[2];
    float* out = (float*)d_out;                 // [100000,64]

    int eb = (E + 255) / 256;
    int n4 = out_size / 4;

    k_count<<<eb, 256>>>(idx, w, (float4*)d_out, n4, E);
    k_scan1<<<NB, SCAN_BS>>>();
    k_scatter<<<eb, 256>>>(idx, w, E);

    int nb4 = (E + 127) / 128;                  // 8 warps x 16 edges per block
    k_main<<<nb4, 256>>>(emb, cf, out, E);
    k_scale<<<(n4 + 255) / 256, 256>>>((float4*)d_out, n4);
}

// round 7
// speedup vs baseline: 2.0002x; 1.3134x over previous
#include <cuda_runtime.h>
#include <stdint.h>

#define NODES   100000
#define MAX_E   3200000
#define SCAN_BS 1024
#define NB      ((NODES + SCAN_BS - 1) / SCAN_BS)   // 98
#define DEN_FX  16777216.0f

// ---------------- scratch ----------------
__device__ unsigned long long g_cd[NODES];   // hi32=count, lo32=den (2^-24 fixed)
__device__ int   g_cursor[NODES];
__device__ float g_invden[NODES];
__device__ int   g_bsum[NB];
__device__ uint4 g_pack[MAX_E];              // {eid, node, bits(w), 0}

// ---------------- helpers ----------------
__device__ __forceinline__ unsigned f2tf32(float f) {
    unsigned r;
    asm("cvt.rna.tf32.f32 %0, %1;" : "=r"(r) : "f"(f));
    return r;
}
__device__ __forceinline__ void mma_tf32(float& d0, float& d1, float& d2, float& d3,
                                         unsigned a0, unsigned a1, unsigned a2, unsigned a3,
                                         unsigned b0, unsigned b1) {
    asm volatile(
        "mma.sync.aligned.m16n8k8.row.col.f32.tf32.tf32.f32 "
        "{%0,%1,%2,%3}, {%4,%5,%6,%7}, {%8,%9}, {%0,%1,%2,%3};"
        : "+f"(d0), "+f"(d1), "+f"(d2), "+f"(d3)
        : "r"(a0), "r"(a1), "r"(a2), "r"(a3), "r"(b0), "r"(b1));
}
__device__ __forceinline__ void redadd(float* p, float v) {
    asm volatile("red.global.add.f32 [%0], %1;" :: "l"(p), "f"(v) : "memory");
}

// butterfly-sum over the 4-lane group (sums edge contributions), then lane c
// writes the u-block mt==c. Destroys a[][].
__device__ __forceinline__ void seg_write(float a[4][2], int node, bool use_red,
                                          float* __restrict__ out, int c, int r4) {
#pragma unroll
    for (int mt = 0; mt < 4; mt++)
#pragma unroll
        for (int h = 0; h < 2; h++) {
            float v = a[mt][h];
            v += __shfl_xor_sync(0xffffffffu, v, 1);
            v += __shfl_xor_sync(0xffffffffu, v, 2);
            a[mt][h] = v;
        }
    if (node < 0) return;
    float vlo = (c == 0) ? a[0][0] : (c == 1) ? a[1][0] : (c == 2) ? a[2][0] : a[3][0];
    float vhi = (c == 0) ? a[0][1] : (c == 1) ? a[1][1] : (c == 2) ? a[2][1] : a[3][1];
    float* dst = out + (size_t)node * 64 + c * 16 + r4;
    if (use_red) { redadd(dst, vlo); redadd(dst + 8, vhi); }
    else         { dst[0] = vlo; dst[8] = vhi; }
}

// ---------------- K1: count + weight-sum + zero out[] ----------------
__global__ void k_count(const int* __restrict__ idx, const float* __restrict__ w,
                        float4* __restrict__ out4, int n4, int E) {
    int e = blockIdx.x * blockDim.x + threadIdx.x;
    for (int z = e; z < n4; z += gridDim.x * blockDim.x)
        out4[z] = make_float4(0.f, 0.f, 0.f, 0.f);
    if (e >= E) return;
    int n = idx[e];
    unsigned fx = __float2uint_rn(w[e] * DEN_FX);
    atomicAdd(&g_cd[n], (1ULL << 32) | (unsigned long long)fx);
}

// ---------------- K2: block-local scan + invden + g_cd re-zero ----------------
__global__ void k_scan1() {
    __shared__ int wsum[32];
    int t = threadIdx.x, b = blockIdx.x;
    int i = b * SCAN_BS + t;
    int lane = t & 31, wq = t >> 5;
    unsigned long long cd = (i < NODES) ? g_cd[i] : 0ULL;
    int v = (int)(cd >> 32);
    if (i < NODES) {
        g_cd[i] = 0ULL;
        g_invden[i] = __fdividef(DEN_FX, (float)(unsigned)(cd & 0xffffffffULL));
    }
    int x = v;
#pragma unroll
    for (int d = 1; d < 32; d <<= 1) {
        int y = __shfl_up_sync(0xffffffffu, x, d);
        if (lane >= d) x += y;
    }
    if (lane == 31) wsum[wq] = x;
    __syncthreads();
    if (wq == 0) {
        int s = wsum[lane];
#pragma unroll
        for (int d = 1; d < 32; d <<= 1) {
            int y = __shfl_up_sync(0xffffffffu, s, d);
            if (lane >= d) s += y;
        }
        wsum[lane] = s;
    }
    __syncthreads();
    int base = wq ? wsum[wq - 1] : 0;
    if (i < NODES) g_cursor[i] = base + x - v;
    if (t == 0) g_bsum[b] = wsum[31];
}

// ---------------- K3: scatter (inline bsum prefix) ----------------
__global__ void k_scatter(const int* __restrict__ idx, const float* __restrict__ w, int E) {
    __shared__ int s_boff[128];
    __shared__ int s_wt[4];
    int t = threadIdx.x;
    int lane = t & 31, wq = t >> 5;
    int v = 0, x = 0;
    if (t < 128) {
        v = (t < NB) ? g_bsum[t] : 0;
        x = v;
#pragma unroll
        for (int d = 1; d < 32; d <<= 1) {
            int y = __shfl_up_sync(0xffffffffu, x, d);
            if (lane >= d) x += y;
        }
        if (lane == 31) s_wt[wq] = x;
    }
    __syncthreads();
    if (t < 128) {
        int addv = 0;
#pragma unroll
        for (int k = 0; k < 4; k++) if (k < wq) addv += s_wt[k];
        s_boff[t] = addv + x - v;
    }
    __syncthreads();
    int e = blockIdx.x * blockDim.x + t;
    if (e >= E) return;
    int n = idx[e];
    int p = atomicAdd(&g_cursor[n], 1) + s_boff[n >> 10];
    g_pack[p] = make_uint4((unsigned)e, (unsigned)n, __float_as_uint(w[e]), 0u);
}

// ---------------- K4: transposed MMA (u=M, edges=N), register-space seg reduce ----------------
#define NWIN 4   // 16-edge windows per warp

__device__ __forceinline__ uint4 ldpk(int i, int l, int E) {
    uint4 pk = make_uint4(0u, 0xFFFFFFFFu, 0u, 0u);   // sentinel: node=-1, w=0
    if (l < 16 && i < E) pk = __ldg(&g_pack[i]);
    return pk;
}

__global__ void __launch_bounds__(128, 5)
k_main(const float* __restrict__ emb, const float* __restrict__ cf,
       float* __restrict__ out, int E) {
    int t = threadIdx.x, wp = t >> 5, l = t & 31;
    int c = l & 3, r4 = l >> 2;
    int wb = (blockIdx.x * 4 + wp) * (NWIN * 16);    // warp's first edge

    // --- A fragments: emb[64,16] -> 32 regs, once per warp ---
    unsigned A[4][2][4];
#pragma unroll
    for (int mt = 0; mt < 4; mt++)
#pragma unroll
        for (int kt = 0; kt < 2; kt++) {
            const float* p = emb + (mt * 16 + r4) * 16 + kt * 8 + c;
            A[mt][kt][0] = f2tf32(__ldg(p));
            A[mt][kt][1] = f2tf32(__ldg(p + 128));    // row +8 (8*16 floats)
            A[mt][kt][2] = f2tf32(__ldg(p + 4));      // k +4
            A[mt][kt][3] = f2tf32(__ldg(p + 132));
        }

    // --- neighbor nodes (decide red vs STG at warp-boundary closes) ---
    int nback = -2, nfwd = -2;
    if (wb > 0)              nback = (int)__ldg(&g_pack[wb - 1]).y;
    if (wb + NWIN * 16 < E)  nfwd  = (int)__ldg(&g_pack[wb + NWIN * 16]).y;

    // --- pipeline prologue ---
    uint4 pkC = ldpk(wb + l, l, E);
    uint4 pkN = ldpk(wb + 16 + l, l, E);
    float rawC[2][4], rawN[2][4];
#pragma unroll
    for (int et = 0; et < 2; et++) {
        unsigned eid = __shfl_sync(0xffffffffu, pkC.x, et * 8 + r4);
        const float* p = cf + (size_t)eid * 16 + c;
        rawC[et][0] = __ldg(p);     rawC[et][1] = __ldg(p + 4);
        rawC[et][2] = __ldg(p + 8); rawC[et][3] = __ldg(p + 12);
    }

    float acc[4][2];
#pragma unroll
    for (int mt = 0; mt < 4; mt++) { acc[mt][0] = 0.f; acc[mt][1] = 0.f; }
    int acc_node = -1;
    bool first = true;
    int prev_last = 0;

#pragma unroll
    for (int j = 0; j < NWIN; j++) {
        // --- prefetch next window's pack+gather ---
        uint4 pkN2 = ldpk(wb + (j + 2) * 16 + l, (j + 2 < NWIN) ? l : 32, E);
        if (j + 1 < NWIN) {
#pragma unroll
            for (int et = 0; et < 2; et++) {
                unsigned eid = __shfl_sync(0xffffffffu, pkN.x, et * 8 + r4);
                const float* p = cf + (size_t)eid * 16 + c;
                rawN[et][0] = __ldg(p);     rawN[et][1] = __ldg(p + 4);
                rawN[et][2] = __ldg(p + 8); rawN[et][3] = __ldg(p + 12);
            }
        }

        // --- window metadata ---
        int nd = (int)pkC.y;
        int ndn = __shfl_down_sync(0xffffffffu, nd, 1);
        unsigned bm = __ballot_sync(0xffffffffu, (l < 15) && (nd != ndn)) & 0x7fffu;
        int node0 = __shfl_sync(0xffffffffu, nd, 0);

        if (j == 0) acc_node = node0;
        else if (prev_last != node0) {                    // cross-window boundary
            seg_write(acc, acc_node, first && (nback == acc_node), out, c, r4);
            first = false;
#pragma unroll
            for (int mt = 0; mt < 4; mt++) { acc[mt][0] = 0.f; acc[mt][1] = 0.f; }
            acc_node = node0;
        }

        // --- two 8-edge tiles ---
#pragma unroll
        for (int et = 0; et < 2; et++) {
            // FIX(R7): boundary between edge 7 and edge 8 (bm bit 7) is a real
            // segment boundary that the intra-tile mask (7 bits) drops. Close
            // the open accumulator at the tile seam when it is set.
            if (et == 1 && (bm & 0x0080u)) {
                seg_write(acc, acc_node, first && (nback == acc_node), out, c, r4);
                first = false;
#pragma unroll
                for (int mt = 0; mt < 4; mt++) { acc[mt][0] = 0.f; acc[mt][1] = 0.f; }
                acc_node = __shfl_sync(0xffffffffu, nd, 8);
            }

            float wv = __uint_as_float(__shfl_sync(0xffffffffu, pkC.z, et * 8 + r4));
            unsigned b0 = f2tf32(rawC[et][0] * wv);
            unsigned b1 = f2tf32(rawC[et][1] * wv);
            unsigned b2 = f2tf32(rawC[et][2] * wv);
            unsigned b3 = f2tf32(rawC[et][3] * wv);

            float d[4][4];
#pragma unroll
            for (int mt = 0; mt < 4; mt++) {
                d[mt][0] = 0.f; d[mt][1] = 0.f; d[mt][2] = 0.f; d[mt][3] = 0.f;
                mma_tf32(d[mt][0], d[mt][1], d[mt][2], d[mt][3],
                         A[mt][0][0], A[mt][0][1], A[mt][0][2], A[mt][0][3], b0, b1);
                mma_tf32(d[mt][0], d[mt][1], d[mt][2], d[mt][3],
                         A[mt][1][0], A[mt][1][1], A[mt][1][2], A[mt][1][3], b2, b3);
                d[mt][0] = fmaxf(d[mt][0], 0.f);
                d[mt][1] = fmaxf(d[mt][1], 0.f);
                d[mt][2] = fmaxf(d[mt][2], 0.f);
                d[mt][3] = fmaxf(d[mt][3], 0.f);
            }

            unsigned tb = (bm >> (et * 8)) & 0x7fu;       // boundaries inside this tile
            if (tb == 0) {                                 // common: whole tile one segment
#pragma unroll
                for (int mt = 0; mt < 4; mt++) {
                    acc[mt][0] += d[mt][0] + d[mt][1];
                    acc[mt][1] += d[mt][2] + d[mt][3];
                }
            } else {
                int sid0 = __popc(tb & ((1u << (2 * c)) - 1));
                int sid1 = sid0 + ((tb >> (2 * c)) & 1);
                // seg 0 continues acc
#pragma unroll
                for (int mt = 0; mt < 4; mt++) {
                    acc[mt][0] += (sid0 == 0 ? d[mt][0] : 0.f) + (sid1 == 0 ? d[mt][1] : 0.f);
                    acc[mt][1] += (sid0 == 0 ? d[mt][2] : 0.f) + (sid1 == 0 ? d[mt][3] : 0.f);
                }
                seg_write(acc, acc_node, first && (nback == acc_node), out, c, r4);
                first = false;
                int last = __popc(tb);
                unsigned rem = tb;
                for (int s = 1; s <= last; s++) {
                    int pos = __ffs(rem) - 1;  rem &= rem - 1;
                    int node_s = __shfl_sync(0xffffffffu, nd, et * 8 + pos + 1);
                    if (s < last) {
                        float v[4][2];
#pragma unroll
                        for (int mt = 0; mt < 4; mt++) {
                            v[mt][0] = (sid0 == s ? d[mt][0] : 0.f) + (sid1 == s ? d[mt][1] : 0.f);
                            v[mt][1] = (sid0 == s ? d[mt][2] : 0.f) + (sid1 == s ? d[mt][3] : 0.f);
                        }
                        seg_write(v, node_s, false, out, c, r4);   // fully interior
                    } else {
#pragma unroll
                        for (int mt = 0; mt < 4; mt++) {
                            acc[mt][0] = (sid0 == s ? d[mt][0] : 0.f) + (sid1 == s ? d[mt][1] : 0.f);
                            acc[mt][1] = (sid0 == s ? d[mt][2] : 0.f) + (sid1 == s ? d[mt][3] : 0.f);
                        }
                        acc_node = node_s;
                    }
                }
            }
        }

        prev_last = __shfl_sync(0xffffffffu, nd, 15);
        pkC = pkN; pkN = pkN2;
#pragma unroll
        for (int et = 0; et < 2; et++)
#pragma unroll
            for (int k = 0; k < 4; k++) rawC[et][k] = rawN[et][k];
    }

    // --- final close: red iff spans backward (never closed) or forward ---
    bool use_red = (first && (nback == acc_node)) || (nfwd == acc_node);
    seg_write(acc, acc_node, use_red, out, c, r4);
}

// ---------------- K5: epilogue scale out *= 1/den ----------------
__global__ void k_scale(float4* __restrict__ out4, int n4) {
    int i = blockIdx.x * blockDim.x + threadIdx.x;
    if (i >= n4) return;
    float s = g_invden[i >> 4];
    float4 v = out4[i];
    v.x *= s; v.y *= s; v.z *= s; v.w *= s;
    out4[i] = v;
}

// ---------------- launch ----------------
extern "C" void kernel_launch(void* const* d_in, const int* in_sizes, int n_in,
                              void* d_out, int out_size) {
    const float* emb = (const float*)d_in[0];   // [64,16]
    const float* cf  = (const float*)d_in[1];   // [E,16]
    const float* w   = (const float*)d_in[2];   // [E]
    const int*   idx = (const int*)d_in[3];     // [E]
    int E = in_sizes[2];
    float* out = (float*)d_out;                 // [100000,64]

    int eb = (E + 255) / 256;
    int n4 = out_size / 4;

    k_count<<<eb, 256>>>(idx, w, (float4*)d_out, n4, E);
    k_scan1<<<NB, SCAN_BS>>>();
    k_scatter<<<eb, 256>>>(idx, w, E);

    int nb4 = (E + 4 * NWIN * 16 - 1) / (4 * NWIN * 16);   // 4 warps x 64 edges
    k_main<<<nb4, 128>>>(emb, cf, out, E);
    k_scale<<<(n4 + 255) / 256, 256>>>((float4*)d_out, n4);
}

// round 8
// speedup vs baseline: 2.0808x; 1.0403x over previous
#include <cuda_runtime.h>
#include <stdint.h>

#define NODES   100000
#define MAX_E   3200000
#define SCAN_BS 1024
#define NB      ((NODES + SCAN_BS - 1) / SCAN_BS)   // 98
#define DEN_FX  16777216.0f

// ---------------- scratch ----------------
__device__ unsigned long long g_cd[NODES];   // hi32=count, lo32=den (2^-24 fixed)
__device__ int   g_cursor[NODES];
__device__ float g_invden[NODES];
__device__ int   g_bsum[NB];
__device__ uint4 g_pack[MAX_E];              // {eid, node, bits(w), 0}

// ---------------- helpers ----------------
__device__ __forceinline__ unsigned f2tf32(float f) {
    unsigned r;
    asm("cvt.rna.tf32.f32 %0, %1;" : "=r"(r) : "f"(f));
    return r;
}
__device__ __forceinline__ void mma_tf32(float& d0, float& d1, float& d2, float& d3,
                                         unsigned a0, unsigned a1, unsigned a2, unsigned a3,
                                         unsigned b0, unsigned b1) {
    asm volatile(
        "mma.sync.aligned.m16n8k8.row.col.f32.tf32.tf32.f32 "
        "{%0,%1,%2,%3}, {%4,%5,%6,%7}, {%8,%9}, {%0,%1,%2,%3};"
        : "+f"(d0), "+f"(d1), "+f"(d2), "+f"(d3)
        : "r"(a0), "r"(a1), "r"(a2), "r"(a3), "r"(b0), "r"(b1));
}
__device__ __forceinline__ void redadd(float* p, float v) {
    asm volatile("red.global.add.f32 [%0], %1;" :: "l"(p), "f"(v) : "memory");
}

// butterfly-sum over the 4-lane group, then lane c writes u-block mt==c.
__device__ __forceinline__ void seg_write(float a[4][2], int node, bool use_red,
                                          float* __restrict__ out, int c, int r4) {
#pragma unroll
    for (int mt = 0; mt < 4; mt++)
#pragma unroll
        for (int h = 0; h < 2; h++) {
            float v = a[mt][h];
            v += __shfl_xor_sync(0xffffffffu, v, 1);
            v += __shfl_xor_sync(0xffffffffu, v, 2);
            a[mt][h] = v;
        }
    if (node < 0) return;
    float vlo = (c == 0) ? a[0][0] : (c == 1) ? a[1][0] : (c == 2) ? a[2][0] : a[3][0];
    float vhi = (c == 0) ? a[0][1] : (c == 1) ? a[1][1] : (c == 2) ? a[2][1] : a[3][1];
    float* dst = out + (size_t)node * 64 + c * 16 + r4;
    if (use_red) { redadd(dst, vlo); redadd(dst + 8, vhi); }
    else         { dst[0] = vlo; dst[8] = vhi; }
}

// ---------------- K1: count + weight-sum + zero out[] ----------------
__global__ void k_count(const int* __restrict__ idx, const float* __restrict__ w,
                        float4* __restrict__ out4, int n4, int E) {
    int e = blockIdx.x * blockDim.x + threadIdx.x;
    for (int z = e; z < n4; z += gridDim.x * blockDim.x)
        out4[z] = make_float4(0.f, 0.f, 0.f, 0.f);
    if (e >= E) return;
    int n = idx[e];
    unsigned fx = __float2uint_rn(w[e] * DEN_FX);
    atomicAdd(&g_cd[n], (1ULL << 32) | (unsigned long long)fx);
}

// ---------------- K2: block-local scan + invden + g_cd re-zero ----------------
__global__ void k_scan1() {
    __shared__ int wsum[32];
    int t = threadIdx.x, b = blockIdx.x;
    int i = b * SCAN_BS + t;
    int lane = t & 31, wq = t >> 5;
    unsigned long long cd = (i < NODES) ? g_cd[i] : 0ULL;
    int v = (int)(cd >> 32);
    if (i < NODES) {
        g_cd[i] = 0ULL;
        g_invden[i] = __fdividef(DEN_FX, (float)(unsigned)(cd & 0xffffffffULL));
    }
    int x = v;
#pragma unroll
    for (int d = 1; d < 32; d <<= 1) {
        int y = __shfl_up_sync(0xffffffffu, x, d);
        if (lane >= d) x += y;
    }
    if (lane == 31) wsum[wq] = x;
    __syncthreads();
    if (wq == 0) {
        int s = wsum[lane];
#pragma unroll
        for (int d = 1; d < 32; d <<= 1) {
            int y = __shfl_up_sync(0xffffffffu, s, d);
            if (lane >= d) s += y;
        }
        wsum[lane] = s;
    }
    __syncthreads();
    int base = wq ? wsum[wq - 1] : 0;
    if (i < NODES) g_cursor[i] = base + x - v;
    if (t == 0) g_bsum[b] = wsum[31];
}

// ---------------- K3: scatter (inline bsum prefix) ----------------
__global__ void k_scatter(const int* __restrict__ idx, const float* __restrict__ w, int E) {
    __shared__ int s_boff[128];
    __shared__ int s_wt[4];
    int t = threadIdx.x;
    int lane = t & 31, wq = t >> 5;
    int v = 0, x = 0;
    if (t < 128) {
        v = (t < NB) ? g_bsum[t] : 0;
        x = v;
#pragma unroll
        for (int d = 1; d < 32; d <<= 1) {
            int y = __shfl_up_sync(0xffffffffu, x, d);
            if (lane >= d) x += y;
        }
        if (lane == 31) s_wt[wq] = x;
    }
    __syncthreads();
    if (t < 128) {
        int addv = 0;
#pragma unroll
        for (int k = 0; k < 4; k++) if (k < wq) addv += s_wt[k];
        s_boff[t] = addv + x - v;
    }
    __syncthreads();
    int e = blockIdx.x * blockDim.x + t;
    if (e >= E) return;
    int n = idx[e];
    int p = atomicAdd(&g_cursor[n], 1) + s_boff[n >> 10];
    g_pack[p] = make_uint4((unsigned)e, (unsigned)n, __float_as_uint(w[e]), 0u);
}

// ---------------- K4: transposed MMA, float4 gather + K-permuted A fragments ----------------
#define NWIN 4   // 16-edge windows per warp

__device__ __forceinline__ uint4 ldpk(int i, int l, int E) {
    uint4 pk = make_uint4(0u, 0xFFFFFFFFu, 0u, 0u);   // sentinel: node=-1, w=0
    if (l < 16 && i < E) pk = __ldg(&g_pack[i]);
    return pk;
}

__global__ void __launch_bounds__(128, 5)
k_main(const float* __restrict__ emb, const float* __restrict__ cf,
       float* __restrict__ out, int E) {
    int t = threadIdx.x, wp = t >> 5, l = t & 31;
    int c = l & 3, r4 = l >> 2;
    int wb = (blockIdx.x * 4 + wp) * (NWIN * 16);    // warp's first edge

    // --- A fragments with PERMUTED k: slot(tig=c) holds k=4c+j so that B can be
    //     a raw float4 (quarter-major) with no lane transpose. MMA contracts
    //     slot-wise, so any k-permutation applied to BOTH A and B is exact. ---
    unsigned A[4][2][4];
#pragma unroll
    for (int mt = 0; mt < 4; mt++)
#pragma unroll
        for (int kt = 0; kt < 2; kt++) {
            const float* p = emb + (mt * 16 + r4) * 16 + 4 * c + 2 * kt;
            A[mt][kt][0] = f2tf32(__ldg(p));          // k = 4c + 2kt     (pairs b0/b2 = vv.x/vv.z)
            A[mt][kt][1] = f2tf32(__ldg(p + 128));    // row +8
            A[mt][kt][2] = f2tf32(__ldg(p + 1));      // k = 4c + 2kt + 1 (pairs b1/b3 = vv.y/vv.w)
            A[mt][kt][3] = f2tf32(__ldg(p + 129));
        }

    // --- neighbor nodes (decide red vs STG at warp-boundary closes) ---
    int nback = -2, nfwd = -2;
    if (wb > 0)              nback = (int)__ldg(&g_pack[wb - 1]).y;
    if (wb + NWIN * 16 < E)  nfwd  = (int)__ldg(&g_pack[wb + NWIN * 16]).y;

    // --- pipeline prologue: pack(win0,win1) + gather(win0) ---
    uint4 pkC = ldpk(wb + l, l, E);
    uint4 pkN = ldpk(wb + 16 + l, l, E);
    float4 rawC[2], rawN[2];
#pragma unroll
    for (int et = 0; et < 2; et++) {
        unsigned eid = __shfl_sync(0xffffffffu, pkC.x, et * 8 + r4);
        rawC[et] = *(const float4*)(cf + (size_t)eid * 16 + 4 * c);   // one LDG.128
    }

    float acc[4][2];
#pragma unroll
    for (int mt = 0; mt < 4; mt++) { acc[mt][0] = 0.f; acc[mt][1] = 0.f; }
    int acc_node = -1;
    bool first = true;
    int prev_last = 0;

#pragma unroll
    for (int j = 0; j < NWIN; j++) {
        // --- prefetch next window ---
        uint4 pkN2 = ldpk(wb + (j + 2) * 16 + l, (j + 2 < NWIN) ? l : 32, E);
        if (j + 1 < NWIN) {
#pragma unroll
            for (int et = 0; et < 2; et++) {
                unsigned eid = __shfl_sync(0xffffffffu, pkN.x, et * 8 + r4);
                rawN[et] = *(const float4*)(cf + (size_t)eid * 16 + 4 * c);
            }
        }

        // --- window metadata ---
        int nd = (int)pkC.y;
        int ndn = __shfl_down_sync(0xffffffffu, nd, 1);
        unsigned bm = __ballot_sync(0xffffffffu, (l < 15) && (nd != ndn)) & 0x7fffu;
        int node0 = __shfl_sync(0xffffffffu, nd, 0);

        if (j == 0) acc_node = node0;
        else if (prev_last != node0) {
            seg_write(acc, acc_node, first && (nback == acc_node), out, c, r4);
            first = false;
#pragma unroll
            for (int mt = 0; mt < 4; mt++) { acc[mt][0] = 0.f; acc[mt][1] = 0.f; }
            acc_node = node0;
        }

        // --- two 8-edge tiles ---
#pragma unroll
        for (int et = 0; et < 2; et++) {
            // boundary between edge 7 and 8 (bm bit 7) closes the open segment
            if (et == 1 && (bm & 0x0080u)) {
                seg_write(acc, acc_node, first && (nback == acc_node), out, c, r4);
                first = false;
#pragma unroll
                for (int mt = 0; mt < 4; mt++) { acc[mt][0] = 0.f; acc[mt][1] = 0.f; }
                acc_node = __shfl_sync(0xffffffffu, nd, 8);
            }

            float wv = __uint_as_float(__shfl_sync(0xffffffffu, pkC.z, et * 8 + r4));
            // quarter-major B: lane c holds cf floats 4c..4c+3 of edge r4
            unsigned b0 = f2tf32(rawC[et].x * wv);
            unsigned b1 = f2tf32(rawC[et].y * wv);
            unsigned b2 = f2tf32(rawC[et].z * wv);
            unsigned b3 = f2tf32(rawC[et].w * wv);

            float d[4][4];
#pragma unroll
            for (int mt = 0; mt < 4; mt++) {
                d[mt][0] = 0.f; d[mt][1] = 0.f; d[mt][2] = 0.f; d[mt][3] = 0.f;
                mma_tf32(d[mt][0], d[mt][1], d[mt][2], d[mt][3],
                         A[mt][0][0], A[mt][0][1], A[mt][0][2], A[mt][0][3], b0, b1);
                mma_tf32(d[mt][0], d[mt][1], d[mt][2], d[mt][3],
                         A[mt][1][0], A[mt][1][1], A[mt][1][2], A[mt][1][3], b2, b3);
                d[mt][0] = fmaxf(d[mt][0], 0.f);
                d[mt][1] = fmaxf(d[mt][1], 0.f);
                d[mt][2] = fmaxf(d[mt][2], 0.f);
                d[mt][3] = fmaxf(d[mt][3], 0.f);
            }

            unsigned tb = (bm >> (et * 8)) & 0x7fu;
            if (tb == 0) {
#pragma unroll
                for (int mt = 0; mt < 4; mt++) {
                    acc[mt][0] += d[mt][0] + d[mt][1];
                    acc[mt][1] += d[mt][2] + d[mt][3];
                }
            } else {
                int sid0 = __popc(tb & ((1u << (2 * c)) - 1));
                int sid1 = sid0 + ((tb >> (2 * c)) & 1);
#pragma unroll
                for (int mt = 0; mt < 4; mt++) {
                    acc[mt][0] += (sid0 == 0 ? d[mt][0] : 0.f) + (sid1 == 0 ? d[mt][1] : 0.f);
                    acc[mt][1] += (sid0 == 0 ? d[mt][2] : 0.f) + (sid1 == 0 ? d[mt][3] : 0.f);
                }
                seg_write(acc, acc_node, first && (nback == acc_node), out, c, r4);
                first = false;
                int last = __popc(tb);
                unsigned rem = tb;
                for (int s = 1; s <= last; s++) {
                    int pos = __ffs(rem) - 1;  rem &= rem - 1;
                    int node_s = __shfl_sync(0xffffffffu, nd, et * 8 + pos + 1);
                    if (s < last) {
                        float v[4][2];
#pragma unroll
                        for (int mt = 0; mt < 4; mt++) {
                            v[mt][0] = (sid0 == s ? d[mt][0] : 0.f) + (sid1 == s ? d[mt][1] : 0.f);
                            v[mt][1] = (sid0 == s ? d[mt][2] : 0.f) + (sid1 == s ? d[mt][3] : 0.f);
                        }
                        seg_write(v, node_s, false, out, c, r4);
                    } else {
#pragma unroll
                        for (int mt = 0; mt < 4; mt++) {
                            acc[mt][0] = (sid0 == s ? d[mt][0] : 0.f) + (sid1 == s ? d[mt][1] : 0.f);
                            acc[mt][1] = (sid0 == s ? d[mt][2] : 0.f) + (sid1 == s ? d[mt][3] : 0.f);
                        }
                        acc_node = node_s;
                    }
                }
            }
        }

        prev_last = __shfl_sync(0xffffffffu, nd, 15);
        pkC = pkN; pkN = pkN2;
        rawC[0] = rawN[0]; rawC[1] = rawN[1];
    }

    bool use_red = (first && (nback == acc_node)) || (nfwd == acc_node);
    seg_write(acc, acc_node, use_red, out, c, r4);
}

// ---------------- K5: epilogue scale out *= 1/den ----------------
__global__ void k_scale(float4* __restrict__ out4, int n4) {
    int i = blockIdx.x * blockDim.x + threadIdx.x;
    if (i >= n4) return;
    float s = g_invden[i >> 4];
    float4 v = out4[i];
    v.x *= s; v.y *= s; v.z *= s; v.w *= s;
    out4[i] = v;
}

// ---------------- launch ----------------
extern "C" void kernel_launch(void* const* d_in, const int* in_sizes, int n_in,
                              void* d_out, int out_size) {
    const float* emb = (const float*)d_in[0];   // [64,16]
    const float* cf  = (const float*)d_in[1];   // [E,16]
    const float* w   = (const float*)d_in[2];   // [E]
    const int*   idx = (const int*)d_in[3];     // [E]
    int E = in_sizes[2];
    float* out = (float*)d_out;                 // [100000,64]

    int eb = (E + 255) / 256;
    int n4 = out_size / 4;

    k_count<<<eb, 256>>>(idx, w, (float4*)d_out, n4, E);
    k_scan1<<<NB, SCAN_BS>>>();
    k_scatter<<<eb, 256>>>(idx, w, E);

    int nb4 = (E + 4 * NWIN * 16 - 1) / (4 * NWIN * 16);   // 4 warps x 64 edges
    k_main<<<nb4, 128>>>(emb, cf, out, E);
    k_scale<<<(n4 + 255) / 256, 256>>>((float4*)d_out, n4);
}

// round 9
// speedup vs baseline: 2.4064x; 1.1565x over previous
#include <cuda_runtime.h>
#include <stdint.h>

#define NODES   100000
#define MAX_E   3200000
#define SCAN_BS 1024
#define NB      ((NODES + SCAN_BS - 1) / SCAN_BS)   // 98
#define DEN_FX  16777216.0f
#define NWIN    8      // 16-edge windows per warp
#define PKS     8      // pack smem stages
#define GSS     4      // gather smem stages

// ---------------- scratch ----------------
__device__ unsigned long long g_cd[NODES];
__device__ int   g_cursor[NODES];
__device__ float g_invden[NODES];
__device__ int   g_bsum[NB];
__device__ uint4 g_pack[MAX_E + 512];        // {eid, node, bits(w), 0}; padded w/ sentinels

// ---------------- helpers ----------------
__device__ __forceinline__ unsigned f2tf32(float f) {
    unsigned r;
    asm("cvt.rna.tf32.f32 %0, %1;" : "=r"(r) : "f"(f));
    return r;
}
__device__ __forceinline__ void mma_tf32(float& d0, float& d1, float& d2, float& d3,
                                         unsigned a0, unsigned a1, unsigned a2, unsigned a3,
                                         unsigned b0, unsigned b1) {
    asm volatile(
        "mma.sync.aligned.m16n8k8.row.col.f32.tf32.tf32.f32 "
        "{%0,%1,%2,%3}, {%4,%5,%6,%7}, {%8,%9}, {%0,%1,%2,%3};"
        : "+f"(d0), "+f"(d1), "+f"(d2), "+f"(d3)
        : "r"(a0), "r"(a1), "r"(a2), "r"(a3), "r"(b0), "r"(b1));
}
__device__ __forceinline__ void redadd(float* p, float v) {
    asm volatile("red.global.add.f32 [%0], %1;" :: "l"(p), "f"(v) : "memory");
}
__device__ __forceinline__ unsigned sptr(const void* p) {
    return (unsigned)__cvta_generic_to_shared(p);
}
#define CPA16(dst, src) asm volatile("cp.async.cg.shared.global [%0], [%1], 16;" :: "r"(dst), "l"(src))
#define CPCOMMIT()      asm volatile("cp.async.commit_group;" ::: "memory")
#define CPWAIT(n)       asm volatile("cp.async.wait_group %0;" :: "n"(n) : "memory")

// butterfly-sum over 4-lane group, lane c writes u-block mt==c. Skips sentinels.
__device__ __forceinline__ void seg_write(float a[4][2], int node, bool use_red,
                                          float* __restrict__ out, int c, int r4) {
#pragma unroll
    for (int mt = 0; mt < 4; mt++)
#pragma unroll
        for (int h = 0; h < 2; h++) {
            float v = a[mt][h];
            v += __shfl_xor_sync(0xffffffffu, v, 1);
            v += __shfl_xor_sync(0xffffffffu, v, 2);
            a[mt][h] = v;
        }
    if ((unsigned)node >= NODES) return;     // sentinel / invalid
    float vlo = (c == 0) ? a[0][0] : (c == 1) ? a[1][0] : (c == 2) ? a[2][0] : a[3][0];
    float vhi = (c == 0) ? a[0][1] : (c == 1) ? a[1][1] : (c == 2) ? a[2][1] : a[3][1];
    float* dst = out + (size_t)node * 64 + c * 16 + r4;
    if (use_red) { redadd(dst, vlo); redadd(dst + 8, vhi); }
    else         { dst[0] = vlo; dst[8] = vhi; }
}

// ---------------- K1: count + weight-sum + zero out[] ----------------
__global__ void k_count(const int* __restrict__ idx, const float* __restrict__ w,
                        float4* __restrict__ out4, int n4, int E) {
    int e = blockIdx.x * blockDim.x + threadIdx.x;
    for (int z = e; z < n4; z += gridDim.x * blockDim.x)
        out4[z] = make_float4(0.f, 0.f, 0.f, 0.f);
    if (e >= E) return;
    int n = idx[e];
    unsigned fx = __float2uint_rn(w[e] * DEN_FX);
    atomicAdd(&g_cd[n], (1ULL << 32) | (unsigned long long)fx);
}

// ---------------- K2: block-local scan + invden + g_cd re-zero ----------------
__global__ void k_scan1() {
    __shared__ int wsum[32];
    int t = threadIdx.x, b = blockIdx.x;
    int i = b * SCAN_BS + t;
    int lane = t & 31, wq = t >> 5;
    unsigned long long cd = (i < NODES) ? g_cd[i] : 0ULL;
    int v = (int)(cd >> 32);
    if (i < NODES) {
        g_cd[i] = 0ULL;
        g_invden[i] = __fdividef(DEN_FX, (float)(unsigned)(cd & 0xffffffffULL));
    }
    int x = v;
#pragma unroll
    for (int d = 1; d < 32; d <<= 1) {
        int y = __shfl_up_sync(0xffffffffu, x, d);
        if (lane >= d) x += y;
    }
    if (lane == 31) wsum[wq] = x;
    __syncthreads();
    if (wq == 0) {
        int s = wsum[lane];
#pragma unroll
        for (int d = 1; d < 32; d <<= 1) {
            int y = __shfl_up_sync(0xffffffffu, s, d);
            if (lane >= d) s += y;
        }
        wsum[lane] = s;
    }
    __syncthreads();
    int base = wq ? wsum[wq - 1] : 0;
    if (i < NODES) g_cursor[i] = base + x - v;
    if (t == 0) g_bsum[b] = wsum[31];
}

// ---------------- K3: scatter (inline bsum prefix) + sentinel padding ----------------
__global__ void k_scatter(const int* __restrict__ idx, const float* __restrict__ w,
                          int E, int Epad) {
    __shared__ int s_boff[128];
    __shared__ int s_wt[4];
    int t = threadIdx.x;
    int lane = t & 31, wq = t >> 5;
    int v = 0, x = 0;
    if (t < 128) {
        v = (t < NB) ? g_bsum[t] : 0;
        x = v;
#pragma unroll
        for (int d = 1; d < 32; d <<= 1) {
            int y = __shfl_up_sync(0xffffffffu, x, d);
            if (lane >= d) x += y;
        }
        if (lane == 31) s_wt[wq] = x;
    }
    __syncthreads();
    if (t < 128) {
        int addv = 0;
#pragma unroll
        for (int k = 0; k < 4; k++) if (k < wq) addv += s_wt[k];
        s_boff[t] = addv + x - v;
    }
    __syncthreads();
    int e = blockIdx.x * blockDim.x + t;
    if (e < Epad - E)                                    // sentinel tail
        g_pack[E + e] = make_uint4(0u, (unsigned)NODES, 0u, 0u);
    if (e >= E) return;
    int n = idx[e];
    int p = atomicAdd(&g_cursor[n], 1) + s_boff[n >> 10];
    g_pack[p] = make_uint4((unsigned)e, (unsigned)n, __float_as_uint(w[e]), 0u);
}

// ---------------- K4: cp.async-pipelined transposed MMA + register seg reduce ----------------
__global__ void __launch_bounds__(128, 6)
k_main(const float* __restrict__ emb, const float* __restrict__ cf,
       float* __restrict__ out, int E) {
    __shared__ __align__(16) uint4 s_pk[4][PKS][16];      // 8 KB
    __shared__ __align__(16) float s_gb[4][GSS][256];     // 16 KB

    int t = threadIdx.x, wp = t >> 5, l = t & 31;
    int c = l & 3, r4 = l >> 2;
    int wb = (blockIdx.x * 4 + wp) * (NWIN * 16);

    // --- A fragments, K-permuted (slot c holds k=4c+j to match quarter-major B) ---
    unsigned A[4][2][4];
#pragma unroll
    for (int mt = 0; mt < 4; mt++)
#pragma unroll
        for (int kt = 0; kt < 2; kt++) {
            const float* p = emb + (mt * 16 + r4) * 16 + 4 * c + 2 * kt;
            A[mt][kt][0] = f2tf32(__ldg(p));
            A[mt][kt][1] = f2tf32(__ldg(p + 128));
            A[mt][kt][2] = f2tf32(__ldg(p + 1));
            A[mt][kt][3] = f2tf32(__ldg(p + 129));
        }

    int nback = -2, nfwd = -2;
    if (wb > 0)              nback = (int)__ldg(&g_pack[wb - 1]).y;
    if (wb + NWIN * 16 < E)  nfwd  = (int)__ldg(&g_pack[wb + NWIN * 16]).y;

    // --- prologue: packs for windows 0..6 (one group), then gathers 0..2 ---
    for (int i = l; i < 112; i += 32)
        CPA16(sptr(&s_pk[wp][i >> 4][i & 15]), g_pack + wb + i);
    CPCOMMIT();
    CPWAIT(0); __syncwarp();
#pragma unroll
    for (int g = 0; g < 3; g++) {
#pragma unroll
        for (int h = 0; h < 2; h++) {
            int i = l + h * 32;
            unsigned eid = s_pk[wp][g][i >> 2].x;
            CPA16(sptr(&s_gb[wp][g][i * 4]), cf + (size_t)eid * 16 + (i & 3) * 4);
        }
        CPCOMMIT();
    }

    float acc[4][2];
#pragma unroll
    for (int mt = 0; mt < 4; mt++) { acc[mt][0] = 0.f; acc[mt][1] = 0.f; }
    int acc_node = -1;
    bool first = true;
    int prev_last = 0;

#pragma unroll 1
    for (int j = 0; j < NWIN; j++) {
        CPWAIT(2); __syncwarp();               // gather j + packs through j+4 resident

        uint4* pkw = s_pk[wp][j & 7];
        int   nd = (int)pkw[l & 15].y;
        float w0 = __uint_as_float(pkw[r4].z);
        float w1 = __uint_as_float(pkw[8 + r4].z);
        int ndn = __shfl_down_sync(0xffffffffu, nd, 1);
        unsigned bm = __ballot_sync(0xffffffffu, (l < 15) && (nd != ndn)) & 0x7fffu;
        int node0 = __shfl_sync(0xffffffffu, nd, 0);

        // --- issue next loads (hidden under this window's compute) ---
        if (j + 3 < NWIN) {
            uint4* pks = s_pk[wp][(j + 3) & 7];
#pragma unroll
            for (int h = 0; h < 2; h++) {
                int i = l + h * 32;
                unsigned eid = pks[i >> 2].x;
                CPA16(sptr(&s_gb[wp][(j + 3) & 3][i * 4]), cf + (size_t)eid * 16 + (i & 3) * 4);
            }
        }
        if (j + 7 < NWIN) {
            if (l < 16)
                CPA16(sptr(&s_pk[wp][(j + 7) & 7][l]), g_pack + wb + (j + 7) * 16 + l);
        }
        CPCOMMIT();

        // --- B values from smem (quarter-major, conflict-free) ---
        const float* gw = s_gb[wp][j & 3];
        float4 B0 = *(const float4*)(gw + r4 * 16 + 4 * c);
        float4 B1 = *(const float4*)(gw + (8 + r4) * 16 + 4 * c);

        if (j == 0) acc_node = node0;
        else if (prev_last != node0) {
            seg_write(acc, acc_node, first && (nback == acc_node), out, c, r4);
            first = false;
#pragma unroll
            for (int mt = 0; mt < 4; mt++) { acc[mt][0] = 0.f; acc[mt][1] = 0.f; }
            acc_node = node0;
        }

#pragma unroll
        for (int et = 0; et < 2; et++) {
            if (et == 1 && (bm & 0x0080u)) {   // seam between edge 7 and 8
                seg_write(acc, acc_node, first && (nback == acc_node), out, c, r4);
                first = false;
#pragma unroll
                for (int mt = 0; mt < 4; mt++) { acc[mt][0] = 0.f; acc[mt][1] = 0.f; }
                acc_node = __shfl_sync(0xffffffffu, nd, 8);
            }

            float wv = et ? w1 : w0;
            float4 Bv = et ? B1 : B0;
            unsigned b0 = f2tf32(Bv.x * wv);
            unsigned b1 = f2tf32(Bv.y * wv);
            unsigned b2 = f2tf32(Bv.z * wv);
            unsigned b3 = f2tf32(Bv.w * wv);

            float d[4][4];
#pragma unroll
            for (int mt = 0; mt < 4; mt++) {
                d[mt][0] = 0.f; d[mt][1] = 0.f; d[mt][2] = 0.f; d[mt][3] = 0.f;
                mma_tf32(d[mt][0], d[mt][1], d[mt][2], d[mt][3],
                         A[mt][0][0], A[mt][0][1], A[mt][0][2], A[mt][0][3], b0, b1);
                mma_tf32(d[mt][0], d[mt][1], d[mt][2], d[mt][3],
                         A[mt][1][0], A[mt][1][1], A[mt][1][2], A[mt][1][3], b2, b3);
                d[mt][0] = fmaxf(d[mt][0], 0.f);
                d[mt][1] = fmaxf(d[mt][1], 0.f);
                d[mt][2] = fmaxf(d[mt][2], 0.f);
                d[mt][3] = fmaxf(d[mt][3], 0.f);
            }

            unsigned tb = (bm >> (et * 8)) & 0x7fu;
            if (tb == 0) {
#pragma unroll
                for (int mt = 0; mt < 4; mt++) {
                    acc[mt][0] += d[mt][0] + d[mt][1];
                    acc[mt][1] += d[mt][2] + d[mt][3];
                }
            } else {
                int sid0 = __popc(tb & ((1u << (2 * c)) - 1));
                int sid1 = sid0 + ((tb >> (2 * c)) & 1);
#pragma unroll
                for (int mt = 0; mt < 4; mt++) {
                    acc[mt][0] += (sid0 == 0 ? d[mt][0] : 0.f) + (sid1 == 0 ? d[mt][1] : 0.f);
                    acc[mt][1] += (sid0 == 0 ? d[mt][2] : 0.f) + (sid1 == 0 ? d[mt][3] : 0.f);
                }
                seg_write(acc, acc_node, first && (nback == acc_node), out, c, r4);
                first = false;
                int last = __popc(tb);
                unsigned rem = tb;
                for (int s = 1; s <= last; s++) {
                    int pos = __ffs(rem) - 1;  rem &= rem - 1;
                    int node_s = __shfl_sync(0xffffffffu, nd, et * 8 + pos + 1);
                    if (s < last) {
                        float vv[4][2];
#pragma unroll
                        for (int mt = 0; mt < 4; mt++) {
                            vv[mt][0] = (sid0 == s ? d[mt][0] : 0.f) + (sid1 == s ? d[mt][1] : 0.f);
                            vv[mt][1] = (sid0 == s ? d[mt][2] : 0.f) + (sid1 == s ? d[mt][3] : 0.f);
                        }
                        seg_write(vv, node_s, false, out, c, r4);
                    } else {
#pragma unroll
                        for (int mt = 0; mt < 4; mt++) {
                            acc[mt][0] = (sid0 == s ? d[mt][0] : 0.f) + (sid1 == s ? d[mt][1] : 0.f);
                            acc[mt][1] = (sid0 == s ? d[mt][2] : 0.f) + (sid1 == s ? d[mt][3] : 0.f);
                        }
                        acc_node = node_s;
                    }
                }
            }
        }

        prev_last = __shfl_sync(0xffffffffu, nd, 15);
    }

    bool use_red = (first && (nback == acc_node)) || (nfwd == acc_node);
    seg_write(acc, acc_node, use_red, out, c, r4);
    CPWAIT(0);                                  // drain before exit
}

// ---------------- K5: epilogue scale out *= 1/den ----------------
__global__ void k_scale(float4* __restrict__ out4, int n4) {
    int i = blockIdx.x * blockDim.x + threadIdx.x;
    if (i >= n4) return;
    float s = g_invden[i >> 4];
    float4 v = out4[i];
    v.x *= s; v.y *= s; v.z *= s; v.w *= s;
    out4[i] = v;
}

// ---------------- launch ----------------
extern "C" void kernel_launch(void* const* d_in, const int* in_sizes, int n_in,
                              void* d_out, int out_size) {
    const float* emb = (const float*)d_in[0];   // [64,16]
    const float* cf  = (const float*)d_in[1];   // [E,16]
    const float* w   = (const float*)d_in[2];   // [E]
    const int*   idx = (const int*)d_in[3];     // [E]
    int E = in_sizes[2];
    float* out = (float*)d_out;                 // [100000,64]

    int eb = (E + 255) / 256;
    int n4 = out_size / 4;
    int Epad = ((E + 511) / 512) * 512;

    k_count<<<eb, 256>>>(idx, w, (float4*)d_out, n4, E);
    k_scan1<<<NB, SCAN_BS>>>();
    k_scatter<<<eb, 256>>>(idx, w, E, Epad);

    k_main<<<Epad / 512, 128>>>(emb, cf, out, E);
    k_scale<<<(n4 + 255) / 256, 256>>>((float4*)d_out, n4);
}